// round 5
// baseline (speedup 1.0000x reference)
#include <cuda_runtime.h>
#include <cuda_bf16.h>
#include <cstdint>

// Problem constants
#define B_     8
#define CIN_   512
#define COUT_  512
#define WDIM_  512
#define H_     64
#define W_     64
#define HW_    (H_ * W_)

typedef unsigned long long u64;

// packed f32x2 helpers (lane0 = low 32 bits)
__device__ __forceinline__ u64 pack2(float lo, float hi) {
    u64 r; asm("mov.b64 %0, {%1, %2};" : "=l"(r) : "f"(lo), "f"(hi)); return r;
}
__device__ __forceinline__ void unpack2(u64 v, float& lo, float& hi) {
    asm("mov.b64 {%0, %1}, %2;" : "=f"(lo), "=f"(hi) : "l"(v));
}
__device__ __forceinline__ void ffma2(u64& d, u64 a, u64 b) {
    asm("fma.rn.f32x2 %0, %1, %2, %0;" : "+l"(d) : "l"(a), "l"(b));
}

// Scratch (device globals — no allocation allowed)
__device__ float g_s[B_ * CIN_];       // style s
__device__ float g_ssq[B_ * CIN_];     // s^2
__device__ float g_wsqT[CIN_ * COUT_]; // sum_kk weight^2, transposed [cin][cout]
__device__ float g_d[B_ * COUT_];      // demod rsqrt

// ---------------------------------------------------------------------------
// Kernel 1: style  s[b][c] = sum_d w[b][d]*affine_w[c][d] + affine_b[c] + 1
// ---------------------------------------------------------------------------
__global__ void style_kernel(const float* __restrict__ w,
                             const float* __restrict__ aw,
                             const float* __restrict__ ab) {
    int b = blockIdx.x;
    int c = threadIdx.x;
    __shared__ float wsh[WDIM_];
    wsh[c] = w[b * WDIM_ + c];
    __syncthreads();
    const float* awr = aw + (size_t)c * WDIM_;
    float acc = 0.f;
#pragma unroll 8
    for (int d = 0; d < WDIM_; ++d) acc += awr[d] * wsh[d];
    float s = acc + ab[c] + 1.0f;
    g_s[b * CIN_ + c] = s;
    g_ssq[b * CIN_ + c] = s * s;
}

// ---------------------------------------------------------------------------
// Kernel 2: wsqT[cin][cout] = sum_tap weight[cout][cin][tap]^2
// ---------------------------------------------------------------------------
__global__ void wsq_kernel(const float* __restrict__ weight) {
    int idx = blockIdx.x * blockDim.x + threadIdx.x;
    if (idx >= COUT_ * CIN_) return;
    int co = idx >> 9;
    int cin = idx & 511;
    const float* wp = weight + (size_t)idx * 9;
    float s = 0.f;
#pragma unroll
    for (int t = 0; t < 9; ++t) s += wp[t] * wp[t];
    g_wsqT[cin * COUT_ + co] = s;
}

// ---------------------------------------------------------------------------
// Kernel 3: demod d[b][co] = rsqrt( sum_cin ssq[b][cin]*wsqT[cin][co] + 1e-8 )
// ---------------------------------------------------------------------------
__global__ void demod_kernel() {
    int b = blockIdx.x;
    int co = threadIdx.x;
    __shared__ float sq[CIN_];
    sq[co] = g_ssq[b * CIN_ + co];
    __syncthreads();
    float acc = 1e-8f;
#pragma unroll 8
    for (int ci = 0; ci < CIN_; ++ci)
        acc += sq[ci] * g_wsqT[ci * COUT_ + co];
    g_d[b * COUT_ + co] = rsqrtf(acc);
}

// ---------------------------------------------------------------------------
// Kernel 4: main conv, inner loop on packed fma.rn.f32x2 (2 FMA / fma-slot)
// Block: 64 cout x (16 rows x 8 cols), 256 threads.
// Thread (row = t&15, co_sub = t>>4): 4 co x 8-pixel row, accs as 4x4 f32x2.
// ---------------------------------------------------------------------------
#define CHUNK 16
#define COT   64
#define RT    16
#define CT    8

__global__ __launch_bounds__(256, 2)
void modconv_kernel(const float* __restrict__ x,
                    const float* __restrict__ weight,
                    const float* __restrict__ noise,
                    const float* __restrict__ bias,
                    float* __restrict__ out) {
    __shared__ __align__(16) float xs[CHUNK][RT + 2][10];   // 11.25 KB
    __shared__ float ws2[COT][CHUNK * 9 + 1];               // 36.25 KB

    const int t = threadIdx.x;
    const int row = t & 15;
    const int co_sub = t >> 4;
    const int b = blockIdx.z;
    const int co0 = blockIdx.x * COT;
    const int tile = blockIdx.y;
    const int h0 = (tile >> 3) * RT;
    const int w0 = (tile & 7) * CT;

    const float* xb = x + (size_t)b * CIN_ * HW_;
    const float* sb = g_s + b * CIN_;

    u64 acc2[4][4];  // [co i][pixel pair p] — lane0 = pixel 2p
#pragma unroll
    for (int i = 0; i < 4; ++i)
#pragma unroll
        for (int p = 0; p < 4; ++p) acc2[i][p] = 0ull;

    for (int cin0 = 0; cin0 < CIN_; cin0 += CHUNK) {
        __syncthreads();
        // ---- load x tile (halo + per-cin modulation) ----
        for (int e = t; e < CHUNK * (RT + 2) * 10; e += 256) {
            int c = e / ((RT + 2) * 10);
            int r = (e / 10) % (RT + 2);
            int cc = e % 10;
            int h = h0 + r - 1;
            int w = w0 + cc - 1;
            float v = 0.f;
            if (h >= 0 && h < H_ && w >= 0 && w < W_)
                v = xb[(cin0 + c) * HW_ + h * W_ + w] * sb[cin0 + c];
            xs[c][r][cc] = v;
        }
        // ---- load weight tile: ws2[col][c*9+tap] ----
        const float* wg = weight + ((size_t)co0 * CIN_ + cin0) * 9;
        for (int e = t; e < COT * CHUNK * 9; e += 256) {
            int col = e / (CHUNK * 9);
            int q = e % (CHUNK * 9);
            ws2[col][q] = wg[(size_t)col * (CIN_ * 9) + q];
        }
        __syncthreads();
        // ---- compute (packed) ----
#pragma unroll 2
        for (int c = 0; c < CHUNK; ++c) {
#pragma unroll
            for (int ky = 0; ky < 3; ++ky) {
                const int qb = c * 9 + ky * 3;
                // even pairs e[k] = (x[2k], x[2k+1]) via aligned LDS.64
                const u64* rowp = (const u64*)&xs[c][row + ky][0];
                u64 ev[5];
#pragma unroll
                for (int k = 0; k < 5; ++k) ev[k] = rowp[k];
                // odd pairs o[k] = (x[2k+1], x[2k+2])
                float el[5], eh[5];
#pragma unroll
                for (int k = 0; k < 5; ++k) unpack2(ev[k], el[k], eh[k]);
                u64 ov[4];
#pragma unroll
                for (int k = 0; k < 4; ++k) ov[k] = pack2(eh[k], el[k + 1]);
#pragma unroll
                for (int i = 0; i < 4; ++i) {
                    const int col = co_sub + 16 * i;
                    const u64 w0p = pack2(ws2[col][qb + 0], ws2[col][qb + 0]);
                    const u64 w1p = pack2(ws2[col][qb + 1], ws2[col][qb + 1]);
                    const u64 w2p = pack2(ws2[col][qb + 2], ws2[col][qb + 2]);
#pragma unroll
                    for (int p = 0; p < 4; ++p) {
                        ffma2(acc2[i][p], w0p, ev[p]);      // tap 0: (x2p, x2p+1)
                        ffma2(acc2[i][p], w1p, ov[p]);      // tap 1: (x2p+1, x2p+2)
                        ffma2(acc2[i][p], w2p, ev[p + 1]);  // tap 2: (x2p+2, x2p+3)
                    }
                }
            }
        }
    }

    // ---- epilogue: demod, noise, bias, leaky relu ----
    const int h = h0 + row;
#pragma unroll
    for (int i = 0; i < 4; ++i) {
        const int co = co0 + co_sub + 16 * i;
        const float dd = g_d[b * COUT_ + co];
        const float bs = bias[co];
        const size_t base = ((size_t)(b * COUT_ + co) * H_ + h) * W_ + w0;
        const float4 n0 = *(const float4*)(noise + base);
        const float4 n1 = *(const float4*)(noise + base + 4);
        float a[8];
#pragma unroll
        for (int p = 0; p < 4; ++p) unpack2(acc2[i][p], a[2 * p], a[2 * p + 1]);
        float r[8];
        r[0] = dd * a[0] + n0.x + bs;
        r[1] = dd * a[1] + n0.y + bs;
        r[2] = dd * a[2] + n0.z + bs;
        r[3] = dd * a[3] + n0.w + bs;
        r[4] = dd * a[4] + n1.x + bs;
        r[5] = dd * a[5] + n1.y + bs;
        r[6] = dd * a[6] + n1.z + bs;
        r[7] = dd * a[7] + n1.w + bs;
#pragma unroll
        for (int j = 0; j < 8; ++j) r[j] = r[j] >= 0.f ? r[j] : 0.2f * r[j];
        *(float4*)(out + base) = make_float4(r[0], r[1], r[2], r[3]);
        *(float4*)(out + base + 4) = make_float4(r[4], r[5], r[6], r[7]);
    }
}

// ---------------------------------------------------------------------------
// Launch. Inputs: x, w, noise, weight, affine_w, affine_b, bias
// ---------------------------------------------------------------------------
extern "C" void kernel_launch(void* const* d_in, const int* in_sizes, int n_in,
                              void* d_out, int out_size) {
    const float* x        = (const float*)d_in[0];
    const float* w        = (const float*)d_in[1];
    const float* noise    = (const float*)d_in[2];
    const float* weight   = (const float*)d_in[3];
    const float* affine_w = (const float*)d_in[4];
    const float* affine_b = (const float*)d_in[5];
    const float* bias     = (const float*)d_in[6];
    float* out = (float*)d_out;

    style_kernel<<<B_, CIN_>>>(w, affine_w, affine_b);
    wsq_kernel<<<(COUT_ * CIN_ + 255) / 256, 256>>>(weight);
    demod_kernel<<<B_, COUT_>>>();

    dim3 grid(COUT_ / COT, (H_ / RT) * (W_ / CT), B_); // (8, 32, 8)
    modconv_kernel<<<grid, 256>>>(x, weight, noise, bias, out);
}

// round 12
// speedup vs baseline: 3.4552x; 3.4552x over previous
#include <cuda_runtime.h>
#include <cuda_bf16.h>
#include <cstdint>

#define B_     8
#define CIN_   512
#define COUT_  512
#define WDIM_  512
#define H_     64
#define W_     64
#define HW_    (H_ * W_)

typedef unsigned int uint;
typedef unsigned short ushort;

// ---------------------------------------------------------------------------
// Helpers (sm_80-level features only: mma.sync, ldmatrix, prmt, bf16 cvt)
// ---------------------------------------------------------------------------
__device__ __forceinline__ uint smem_u32(const void* p) {
    uint a;
    asm("{ .reg .u64 t; cvta.to.shared.u64 t, %1; cvt.u32.u64 %0, t; }" : "=r"(a) : "l"(p));
    return a;
}
__device__ __forceinline__ uint prmt(uint a, uint b, uint s) {
    uint d; asm("prmt.b32 %0, %1, %2, %3;" : "=r"(d) : "r"(a), "r"(b), "r"(s)); return d;
}
// pack float -> (bf16 hi | bf16 lo << 16), lo = bf16(v - f32(hi))
__device__ __forceinline__ uint packsplit(float v) {
    ushort h; asm("cvt.rn.bf16.f32 %0, %1;" : "=h"(h) : "f"(v));
    float fh = __uint_as_float(((uint)h) << 16);
    float r = v - fh;
    ushort l; asm("cvt.rn.bf16.f32 %0, %1;" : "=h"(l) : "f"(r));
    return (uint)h | ((uint)l << 16);
}
__device__ __forceinline__ void ldm_x4(uint* r, uint addr) {
    asm volatile("ldmatrix.sync.aligned.m8n8.x4.shared.b16 {%0,%1,%2,%3}, [%4];"
                 : "=r"(r[0]), "=r"(r[1]), "=r"(r[2]), "=r"(r[3]) : "r"(addr));
}
__device__ __forceinline__ void ldm_x2t(uint* r, uint addr) {
    asm volatile("ldmatrix.sync.aligned.m8n8.x2.trans.shared.b16 {%0,%1}, [%2];"
                 : "=r"(r[0]), "=r"(r[1]) : "r"(addr));
}
__device__ __forceinline__ void mma_bf16(float* c, const uint* a, const uint* b) {
    asm volatile(
        "mma.sync.aligned.m16n8k16.row.col.f32.bf16.bf16.f32 "
        "{%0,%1,%2,%3}, {%4,%5,%6,%7}, {%8,%9}, {%0,%1,%2,%3};"
        : "+f"(c[0]), "+f"(c[1]), "+f"(c[2]), "+f"(c[3])
        : "r"(a[0]), "r"(a[1]), "r"(a[2]), "r"(a[3]), "r"(b[0]), "r"(b[1]));
}

// ---------------------------------------------------------------------------
// Scratch (device globals)
// ---------------------------------------------------------------------------
__device__ float g_s[B_ * CIN_];
__device__ float g_ssq[B_ * CIN_];
__device__ float g_wsqT[CIN_ * COUT_];
__device__ float g_d[B_ * COUT_];
__device__ uint  g_x2[B_ * CIN_ * HW_];        // modulated x, packed bf16 split (67MB)
__device__ uint  g_w2[9 * COUT_ * CIN_];       // weights per tap, packed bf16 split

// ---------------------------------------------------------------------------
// Prep kernels
// ---------------------------------------------------------------------------
__global__ void style_kernel(const float* __restrict__ w,
                             const float* __restrict__ aw,
                             const float* __restrict__ ab) {
    int b = blockIdx.x;
    int c = threadIdx.x;
    __shared__ float wsh[WDIM_];
    wsh[c] = w[b * WDIM_ + c];
    __syncthreads();
    const float* awr = aw + (size_t)c * WDIM_;
    float acc = 0.f;
#pragma unroll 8
    for (int d = 0; d < WDIM_; ++d) acc += awr[d] * wsh[d];
    float s = acc + ab[c] + 1.0f;
    g_s[b * CIN_ + c] = s;
    g_ssq[b * CIN_ + c] = s * s;
}

__global__ void wsq_kernel(const float* __restrict__ weight) {
    int idx = blockIdx.x * blockDim.x + threadIdx.x;
    if (idx >= COUT_ * CIN_) return;
    int co = idx >> 9;
    int cin = idx & 511;
    const float* wp = weight + (size_t)idx * 9;
    float s = 0.f;
#pragma unroll
    for (int t = 0; t < 9; ++t) s += wp[t] * wp[t];
    g_wsqT[cin * COUT_ + co] = s;
}

__global__ void demod_kernel() {
    int b = blockIdx.x;
    int co = threadIdx.x;
    __shared__ float sq[CIN_];
    sq[co] = g_ssq[b * CIN_ + co];
    __syncthreads();
    float acc = 1e-8f;
#pragma unroll 8
    for (int ci = 0; ci < CIN_; ++ci)
        acc += sq[ci] * g_wsqT[ci * COUT_ + co];
    g_d[b * COUT_ + co] = rsqrtf(acc);
}

// split modulated x: g_x2[b][ci][p] = packsplit(x * s)
__global__ void split_x_kernel(const float* __restrict__ x) {
    int idx = blockIdx.x * 256 + threadIdx.x;      // 16,777,216 total
    int b = idx >> 21;
    int ci = (idx >> 12) & 511;
    float s = g_s[b * CIN_ + ci];
    g_x2[idx] = packsplit(x[idx] * s);
}

// split weights per tap: g_w2[tap][co][ci]
__global__ void split_w_kernel(const float* __restrict__ weight) {
    int idx = blockIdx.x * 256 + threadIdx.x;      // 2,359,296 total
    int tap = idx >> 18;
    int co = (idx >> 9) & 511;
    int ci = idx & 511;
    g_w2[idx] = packsplit(weight[((size_t)co * CIN_ + ci) * 9 + tap]);
}

// ---------------------------------------------------------------------------
// Main conv: mma.sync bf16 implicit GEMM, 3-pass split (hh + hl + lh)
// CTA: 128 cout x 128 pixels (2 rows). 8 warps: wm=wid&3 (m32), wn=wid>>2 (n64).
// 288 stages: 32 cin-chunks x 9 taps, k16 each.
// ---------------------------------------------------------------------------
__global__ __launch_bounds__(256)
void modconv_mma_kernel(const float* __restrict__ noise,
                        const float* __restrict__ bias,
                        float* __restrict__ out) {
    __shared__ __align__(16) ushort Ahi[128][24], Alo[128][24];  // stride 24 -> conflict-free ldmatrix
    __shared__ __align__(16) ushort Bhi[16][136], Blo[16][136];  // stride 136 -> conflict-free

    const int t = threadIdx.x;
    const int lane = t & 31;
    const int wid = t >> 5;
    const int wm = wid & 3;        // m32 block
    const int wn = wid >> 2;       // n64 block (= image row select)
    const int b = blockIdx.z;
    const int co0 = blockIdx.x * 128;
    const int h0 = blockIdx.y * 2;

    float acc[2][8][4];
#pragma unroll
    for (int mt = 0; mt < 2; ++mt)
#pragma unroll
        for (int nt = 0; nt < 8; ++nt)
#pragma unroll
            for (int i = 0; i < 4; ++i) acc[mt][nt][i] = 0.f;

    // lane-fixed ldmatrix byte offsets
    const uint a_lane = (uint)((lane & 15) * 48 + (lane >> 4) * 16);   // row*(24*2) + koff*2
    const uint b_lane = (uint)((lane & 15) * 272);                     // row*(136*2)
    const uint Ahi_b = smem_u32(&Ahi[0][0]);
    const uint Alo_b = smem_u32(&Alo[0][0]);
    const uint Bhi_b = smem_u32(&Bhi[0][0]);
    const uint Blo_b = smem_u32(&Blo[0][0]);

    // A-build thread map: m = t>>1, k0 = (t&1)*8
    const int am = t >> 1;
    const int ak0 = (t & 1) * 8;
    // B-build thread map: k = t>>4, n0 = (t&15)*8
    const int bk = t >> 4;
    const int bn0 = (t & 15) * 8;

    for (int chunk = 0; chunk < 32; ++chunk) {
        const int ci0 = chunk * 16;
#pragma unroll 1
        for (int tap = 0; tap < 9; ++tap) {
            const int dy = tap / 3 - 1;
            const int dx = tap % 3 - 1;
            __syncthreads();   // protect smem from previous stage's ldmatrix

            // ---- A tile: 128m x 16k from g_w2 ----
            {
                const uint4* src = (const uint4*)(g_w2 + (((size_t)tap * 512 + co0 + am) << 9) + ci0 + ak0);
                uint4 u0 = src[0], u1 = src[1];
                uint4 hv, lv;
                hv.x = prmt(u0.x, u0.y, 0x5410); hv.y = prmt(u0.z, u0.w, 0x5410);
                hv.z = prmt(u1.x, u1.y, 0x5410); hv.w = prmt(u1.z, u1.w, 0x5410);
                lv.x = prmt(u0.x, u0.y, 0x7632); lv.y = prmt(u0.z, u0.w, 0x7632);
                lv.z = prmt(u1.x, u1.y, 0x7632); lv.w = prmt(u1.z, u1.w, 0x7632);
                *(uint4*)&Ahi[am][ak0] = hv;
                *(uint4*)&Alo[am][ak0] = lv;
            }
            // ---- B tile: 16k x 128n from g_x2 (tap-shifted, zero-padded) ----
            {
                const int hh = h0 + (bn0 >> 6) + dy;
                const int wb = (bn0 & 63) + dx;
                uint u[8];
                if (hh >= 0 && hh < H_) {
                    const uint* xrow = g_x2 + (((size_t)(b * CIN_ + ci0 + bk) * H_ + hh) << 6);
#pragma unroll
                    for (int j = 0; j < 8; ++j) {
                        int ww = wb + j;
                        u[j] = (ww >= 0 && ww < W_) ? xrow[ww] : 0u;
                    }
                } else {
#pragma unroll
                    for (int j = 0; j < 8; ++j) u[j] = 0u;
                }
                uint4 hv, lv;
                hv.x = prmt(u[0], u[1], 0x5410); hv.y = prmt(u[2], u[3], 0x5410);
                hv.z = prmt(u[4], u[5], 0x5410); hv.w = prmt(u[6], u[7], 0x5410);
                lv.x = prmt(u[0], u[1], 0x7632); lv.y = prmt(u[2], u[3], 0x7632);
                lv.z = prmt(u[4], u[5], 0x7632); lv.w = prmt(u[6], u[7], 0x7632);
                *(uint4*)&Bhi[bk][bn0] = hv;
                *(uint4*)&Blo[bk][bn0] = lv;
            }
            __syncthreads();

            // ---- fragments + mma ----
            uint ah[2][4], al[2][4];
#pragma unroll
            for (int mt = 0; mt < 2; ++mt) {
                uint mb = (uint)((wm * 32 + mt * 16) * 48);
                ldm_x4(ah[mt], Ahi_b + mb + a_lane);
                ldm_x4(al[mt], Alo_b + mb + a_lane);
            }
#pragma unroll
            for (int nt = 0; nt < 8; ++nt) {
                uint nb = (uint)((wn * 64 + nt * 8) * 2);
                uint bh[2], bl[2];
                ldm_x2t(bh, Bhi_b + b_lane + nb);
                ldm_x2t(bl, Blo_b + b_lane + nb);
#pragma unroll
                for (int mt = 0; mt < 2; ++mt) {
                    mma_bf16(acc[mt][nt], ah[mt], bh);   // hi*hi
                    mma_bf16(acc[mt][nt], ah[mt], bl);   // hi*lo
                    mma_bf16(acc[mt][nt], al[mt], bh);   // lo*hi
                }
            }
        }
    }

    // ---- epilogue: demod + noise + bias + leaky ----
    const int h = h0 + wn;
#pragma unroll
    for (int mt = 0; mt < 2; ++mt) {
        const int coa = co0 + wm * 32 + mt * 16 + (lane >> 2);
        const int cob = coa + 8;
        const float dda = g_d[b * COUT_ + coa], dba = bias[coa];
        const float ddb = g_d[b * COUT_ + cob], dbb = bias[cob];
        const size_t rowa = ((size_t)(b * COUT_ + coa) * H_ + h) * W_;
        const size_t rowb = ((size_t)(b * COUT_ + cob) * H_ + h) * W_;
#pragma unroll
        for (int nt = 0; nt < 8; ++nt) {
            const int wcol = nt * 8 + (lane & 3) * 2;
            float2 na = *(const float2*)(noise + rowa + wcol);
            float2 nb = *(const float2*)(noise + rowb + wcol);
            float r0 = dda * acc[mt][nt][0] + na.x + dba;
            float r1 = dda * acc[mt][nt][1] + na.y + dba;
            float r2 = ddb * acc[mt][nt][2] + nb.x + dbb;
            float r3 = ddb * acc[mt][nt][3] + nb.y + dbb;
            r0 = r0 >= 0.f ? r0 : 0.2f * r0;
            r1 = r1 >= 0.f ? r1 : 0.2f * r1;
            r2 = r2 >= 0.f ? r2 : 0.2f * r2;
            r3 = r3 >= 0.f ? r3 : 0.2f * r3;
            *(float2*)(out + rowa + wcol) = make_float2(r0, r1);
            *(float2*)(out + rowb + wcol) = make_float2(r2, r3);
        }
    }
}

// ---------------------------------------------------------------------------
// Launch. Inputs: x, w, noise, weight, affine_w, affine_b, bias
// ---------------------------------------------------------------------------
extern "C" void kernel_launch(void* const* d_in, const int* in_sizes, int n_in,
                              void* d_out, int out_size) {
    const float* x        = (const float*)d_in[0];
    const float* w        = (const float*)d_in[1];
    const float* noise    = (const float*)d_in[2];
    const float* weight   = (const float*)d_in[3];
    const float* affine_w = (const float*)d_in[4];
    const float* affine_b = (const float*)d_in[5];
    const float* bias     = (const float*)d_in[6];
    float* out = (float*)d_out;

    style_kernel<<<B_, CIN_>>>(w, affine_w, affine_b);
    wsq_kernel<<<(COUT_ * CIN_ + 255) / 256, 256>>>(weight);
    demod_kernel<<<B_, COUT_>>>();
    split_x_kernel<<<(B_ * CIN_ * HW_) / 256, 256>>>(x);       // needs g_s
    split_w_kernel<<<(9 * COUT_ * CIN_) / 256, 256>>>(weight);

    dim3 grid(COUT_ / 128, H_ / 2, B_);   // (4, 32, 8) = 1024 CTAs
    modconv_mma_kernel<<<grid, 256>>>(noise, bias, out);
}

// round 13
// speedup vs baseline: 3.4674x; 1.0035x over previous
#include <cuda_runtime.h>
#include <cuda_bf16.h>
#include <cstdint>

#define B_     8
#define CIN_   512
#define COUT_  512
#define WDIM_  512
#define H_     64
#define W_     64
#define HW_    (H_ * W_)

typedef unsigned int uint;
typedef unsigned short ushort;

// ---------------------------------------------------------------------------
// Helpers (sm_80-level: mma.sync, ldmatrix, prmt, bf16 cvt)
// ---------------------------------------------------------------------------
__device__ __forceinline__ uint smem_u32(const void* p) {
    uint a;
    asm("{ .reg .u64 t; cvta.to.shared.u64 t, %1; cvt.u32.u64 %0, t; }" : "=r"(a) : "l"(p));
    return a;
}
__device__ __forceinline__ uint prmt(uint a, uint b, uint s) {
    uint d; asm("prmt.b32 %0, %1, %2, %3;" : "=r"(d) : "r"(a), "r"(b), "r"(s)); return d;
}
__device__ __forceinline__ uint packsplit(float v) {
    ushort h; asm("cvt.rn.bf16.f32 %0, %1;" : "=h"(h) : "f"(v));
    float fh = __uint_as_float(((uint)h) << 16);
    float r = v - fh;
    ushort l; asm("cvt.rn.bf16.f32 %0, %1;" : "=h"(l) : "f"(r));
    return (uint)h | ((uint)l << 16);
}
__device__ __forceinline__ void ldm_x4(uint* r, uint addr) {
    asm volatile("ldmatrix.sync.aligned.m8n8.x4.shared.b16 {%0,%1,%2,%3}, [%4];"
                 : "=r"(r[0]), "=r"(r[1]), "=r"(r[2]), "=r"(r[3]) : "r"(addr));
}
__device__ __forceinline__ void ldm_x2t(uint* r, uint addr) {
    asm volatile("ldmatrix.sync.aligned.m8n8.x2.trans.shared.b16 {%0,%1}, [%2];"
                 : "=r"(r[0]), "=r"(r[1]) : "r"(addr));
}
__device__ __forceinline__ void mma_bf16(float* c, const uint* a, const uint* b) {
    asm volatile(
        "mma.sync.aligned.m16n8k16.row.col.f32.bf16.bf16.f32 "
        "{%0,%1,%2,%3}, {%4,%5,%6,%7}, {%8,%9}, {%0,%1,%2,%3};"
        : "+f"(c[0]), "+f"(c[1]), "+f"(c[2]), "+f"(c[3])
        : "r"(a[0]), "r"(a[1]), "r"(a[2]), "r"(a[3]), "r"(b[0]), "r"(b[1]));
}

// ---------------------------------------------------------------------------
// Scratch (device globals)
// ---------------------------------------------------------------------------
__device__ float  g_s[B_ * CIN_];
__device__ float  g_ssq[B_ * CIN_];
__device__ float  g_wsqT[CIN_ * COUT_];
__device__ float  g_d[B_ * COUT_];
__device__ uint   g_x2[B_ * CIN_ * HW_];       // modulated x, packed (hi | lo<<16)
__device__ ushort g_whi[9 * COUT_ * CIN_];     // weight hi per tap
__device__ ushort g_wlo[9 * COUT_ * CIN_];     // weight lo per tap

// ---------------------------------------------------------------------------
// Prep kernels
// ---------------------------------------------------------------------------
__global__ void style_kernel(const float* __restrict__ w,
                             const float* __restrict__ aw,
                             const float* __restrict__ ab) {
    int b = blockIdx.x;
    int c = threadIdx.x;
    __shared__ float wsh[WDIM_];
    wsh[c] = w[b * WDIM_ + c];
    __syncthreads();
    const float* awr = aw + (size_t)c * WDIM_;
    float acc = 0.f;
#pragma unroll 8
    for (int d = 0; d < WDIM_; ++d) acc += awr[d] * wsh[d];
    float s = acc + ab[c] + 1.0f;
    g_s[b * CIN_ + c] = s;
    g_ssq[b * CIN_ + c] = s * s;
}

__global__ void wsq_kernel(const float* __restrict__ weight) {
    int idx = blockIdx.x * blockDim.x + threadIdx.x;
    if (idx >= COUT_ * CIN_) return;
    const float* wp = weight + (size_t)idx * 9;
    float s = 0.f;
#pragma unroll
    for (int t = 0; t < 9; ++t) s += wp[t] * wp[t];
    g_wsqT[(idx & 511) * COUT_ + (idx >> 9)] = s;
}

__global__ void demod_kernel() {
    int b = blockIdx.x;
    int co = threadIdx.x;
    __shared__ float sq[CIN_];
    sq[co] = g_ssq[b * CIN_ + co];
    __syncthreads();
    float acc = 1e-8f;
#pragma unroll 8
    for (int ci = 0; ci < CIN_; ++ci)
        acc += sq[ci] * g_wsqT[ci * COUT_ + co];
    g_d[b * COUT_ + co] = rsqrtf(acc);
}

__global__ void split_x_kernel(const float* __restrict__ x) {
    int idx = blockIdx.x * 256 + threadIdx.x;
    int b = idx >> 21;
    int ci = (idx >> 12) & 511;
    g_x2[idx] = packsplit(x[idx] * g_s[b * CIN_ + ci]);
}

__global__ void split_w_kernel(const float* __restrict__ weight) {
    int idx = blockIdx.x * 256 + threadIdx.x;      // tap*512*512 + co*512 + ci
    int tap = idx >> 18;
    int co = (idx >> 9) & 511;
    int ci = idx & 511;
    uint p = packsplit(weight[((size_t)co * CIN_ + ci) * 9 + tap]);
    g_whi[idx] = (ushort)(p & 0xFFFF);
    g_wlo[idx] = (ushort)(p >> 16);
}

// ---------------------------------------------------------------------------
// Main conv: mma.sync bf16 implicit GEMM, 3-pass split, double-buffered
// pipeline (one __syncthreads per stage; LDG for s+1 overlaps mma of s).
// CTA: 128 cout x 128 pixels (2 rows). 8 warps: wm=wid&3 (m32), wn=wid>>2 (n64).
// 288 stages: 32 cin-chunks x 9 taps, k16 each.
// ---------------------------------------------------------------------------
__global__ __launch_bounds__(256)
void modconv_mma_kernel(const float* __restrict__ noise,
                        const float* __restrict__ bias,
                        float* __restrict__ out) {
    __shared__ __align__(16) ushort Ahi[2][128][24], Alo[2][128][24];  // 24 KB
    __shared__ __align__(16) ushort Bhi[2][16][136], Blo[2][16][136];  // 17 KB

    const int t = threadIdx.x;
    const int lane = t & 31;
    const int wid = t >> 5;
    const int wm = wid & 3;
    const int wn = wid >> 2;
    const int b = blockIdx.z;
    const int co0 = blockIdx.x * 128;
    const int h0 = blockIdx.y * 2;

    float acc[2][8][4];
#pragma unroll
    for (int mt = 0; mt < 2; ++mt)
#pragma unroll
        for (int nt = 0; nt < 8; ++nt)
#pragma unroll
            for (int i = 0; i < 4; ++i) acc[mt][nt][i] = 0.f;

    const uint a_lane = (uint)((lane & 15) * 48 + (lane >> 4) * 16);
    const uint b_lane = (uint)((lane & 15) * 272);

    // build-thread maps
    const int am = t >> 1;            // A row (cout-sub)
    const int ak0 = (t & 1) * 8;      // A k offset (8 ushorts = 16B)
    const int bk = t >> 4;            // B k row
    const int bn0 = (t & 15) * 8;     // B pixel offset

    // ---- stage loaders ----
    uint4 ra_h, ra_l;     // A staging regs
    uint  rb[8];          // B staging regs (packed)

    auto load_stage = [&](int st) {
        const int chunk = st / 9;
        const int tap = st - chunk * 9;
        const int ci0 = chunk * 16;
        // A
        const ushort* wh = g_whi + (((size_t)tap * 512 + co0 + am) << 9) + ci0 + ak0;
        const ushort* wl = g_wlo + (((size_t)tap * 512 + co0 + am) << 9) + ci0 + ak0;
        ra_h = *(const uint4*)wh;
        ra_l = *(const uint4*)wl;
        // B (tap-shifted, zero-padded)
        const int dy = tap / 3 - 1;
        const int dx = tap % 3 - 1;
        const int hh = h0 + (bn0 >> 6) + dy;
        const int wb = (bn0 & 63) + dx;
        if (hh >= 0 && hh < H_) {
            const uint* xrow = g_x2 + (((size_t)(b * CIN_ + ci0 + bk) * H_ + hh) << 6);
#pragma unroll
            for (int j = 0; j < 8; ++j) {
                int ww = wb + j;
                rb[j] = (ww >= 0 && ww < W_) ? xrow[ww] : 0u;
            }
        } else {
#pragma unroll
            for (int j = 0; j < 8; ++j) rb[j] = 0u;
        }
    };
    auto store_stage = [&](int buf) {
        *(uint4*)&Ahi[buf][am][ak0] = ra_h;
        *(uint4*)&Alo[buf][am][ak0] = ra_l;
        uint4 hv, lv;
        hv.x = prmt(rb[0], rb[1], 0x5410); hv.y = prmt(rb[2], rb[3], 0x5410);
        hv.z = prmt(rb[4], rb[5], 0x5410); hv.w = prmt(rb[6], rb[7], 0x5410);
        lv.x = prmt(rb[0], rb[1], 0x7632); lv.y = prmt(rb[2], rb[3], 0x7632);
        lv.z = prmt(rb[4], rb[5], 0x7632); lv.w = prmt(rb[6], rb[7], 0x7632);
        *(uint4*)&Bhi[buf][bk][bn0] = hv;
        *(uint4*)&Blo[buf][bk][bn0] = lv;
    };

    // prologue: stage 0 into buf 0
    load_stage(0);
    store_stage(0);
    __syncthreads();

#pragma unroll 1
    for (int st = 0; st < 288; ++st) {
        const int buf = st & 1;
        // issue next stage's loads first (overlap with mma)
        if (st + 1 < 288) load_stage(st + 1);

        // ---- fragments + mma from buf ----
        const uint AhiB = smem_u32(&Ahi[buf][0][0]);
        const uint AloB = smem_u32(&Alo[buf][0][0]);
        const uint BhiB = smem_u32(&Bhi[buf][0][0]);
        const uint BloB = smem_u32(&Blo[buf][0][0]);
        uint ah[2][4], al[2][4];
#pragma unroll
        for (int mt = 0; mt < 2; ++mt) {
            uint mb = (uint)((wm * 32 + mt * 16) * 48);
            ldm_x4(ah[mt], AhiB + mb + a_lane);
            ldm_x4(al[mt], AloB + mb + a_lane);
        }
#pragma unroll
        for (int nt = 0; nt < 8; ++nt) {
            uint nb = (uint)((wn * 64 + nt * 8) * 2);
            uint bh[2], bl[2];
            ldm_x2t(bh, BhiB + b_lane + nb);
            ldm_x2t(bl, BloB + b_lane + nb);
#pragma unroll
            for (int mt = 0; mt < 2; ++mt) {
                mma_bf16(acc[mt][nt], ah[mt], bh);   // hi*hi
                mma_bf16(acc[mt][nt], ah[mt], bl);   // hi*lo
                mma_bf16(acc[mt][nt], al[mt], bh);   // lo*hi
            }
        }

        // store next stage into other buffer; single sync per stage
        if (st + 1 < 288) store_stage(buf ^ 1);
        __syncthreads();
    }

    // ---- epilogue: demod + noise + bias + leaky ----
    const int h = h0 + wn;
#pragma unroll
    for (int mt = 0; mt < 2; ++mt) {
        const int coa = co0 + wm * 32 + mt * 16 + (lane >> 2);
        const int cob = coa + 8;
        const float dda = g_d[b * COUT_ + coa], dba = bias[coa];
        const float ddb = g_d[b * COUT_ + cob], dbb = bias[cob];
        const size_t rowa = ((size_t)(b * COUT_ + coa) * H_ + h) * W_;
        const size_t rowb = ((size_t)(b * COUT_ + cob) * H_ + h) * W_;
#pragma unroll
        for (int nt = 0; nt < 8; ++nt) {
            const int wcol = nt * 8 + (lane & 3) * 2;
            float2 na = *(const float2*)(noise + rowa + wcol);
            float2 nb = *(const float2*)(noise + rowb + wcol);
            float r0 = dda * acc[mt][nt][0] + na.x + dba;
            float r1 = dda * acc[mt][nt][1] + na.y + dba;
            float r2 = ddb * acc[mt][nt][2] + nb.x + dbb;
            float r3 = ddb * acc[mt][nt][3] + nb.y + dbb;
            r0 = r0 >= 0.f ? r0 : 0.2f * r0;
            r1 = r1 >= 0.f ? r1 : 0.2f * r1;
            r2 = r2 >= 0.f ? r2 : 0.2f * r2;
            r3 = r3 >= 0.f ? r3 : 0.2f * r3;
            *(float2*)(out + rowa + wcol) = make_float2(r0, r1);
            *(float2*)(out + rowb + wcol) = make_float2(r2, r3);
        }
    }
}

// ---------------------------------------------------------------------------
// Launch. Inputs: x, w, noise, weight, affine_w, affine_b, bias
// ---------------------------------------------------------------------------
extern "C" void kernel_launch(void* const* d_in, const int* in_sizes, int n_in,
                              void* d_out, int out_size) {
    const float* x        = (const float*)d_in[0];
    const float* w        = (const float*)d_in[1];
    const float* noise    = (const float*)d_in[2];
    const float* weight   = (const float*)d_in[3];
    const float* affine_w = (const float*)d_in[4];
    const float* affine_b = (const float*)d_in[5];
    const float* bias     = (const float*)d_in[6];
    float* out = (float*)d_out;

    style_kernel<<<B_, CIN_>>>(w, affine_w, affine_b);
    wsq_kernel<<<(COUT_ * CIN_ + 255) / 256, 256>>>(weight);
    demod_kernel<<<B_, COUT_>>>();
    split_x_kernel<<<(B_ * CIN_ * HW_) / 256, 256>>>(x);
    split_w_kernel<<<(9 * COUT_ * CIN_) / 256, 256>>>(weight);

    dim3 grid(COUT_ / 128, H_ / 2, B_);   // (4, 32, 8) = 1024 CTAs
    modconv_mma_kernel<<<grid, 256>>>(noise, bias, out);
}

// round 14
// speedup vs baseline: 4.5240x; 1.3047x over previous
#include <cuda_runtime.h>
#include <cuda_fp16.h>
#include <cstdint>

#define B_     8
#define CIN_   512
#define COUT_  512
#define WDIM_  512
#define H_     64
#define W_     64
#define HW_    (H_ * W_)

typedef unsigned int uint;
typedef unsigned short ushort;

// ---------------------------------------------------------------------------
// Helpers (sm_80-level: mma.sync, ldmatrix, f16 cvt)
// ---------------------------------------------------------------------------
__device__ __forceinline__ uint smem_u32(const void* p) {
    uint a;
    asm("{ .reg .u64 t; cvta.to.shared.u64 t, %1; cvt.u32.u64 %0, t; }" : "=r"(a) : "l"(p));
    return a;
}
__device__ __forceinline__ ushort f16_of(float v) {
    ushort h; asm("cvt.rn.f16.f32 %0, %1;" : "=h"(h) : "f"(v)); return h;
}
__device__ __forceinline__ void ldm_x4(uint* r, uint addr) {
    asm volatile("ldmatrix.sync.aligned.m8n8.x4.shared.b16 {%0,%1,%2,%3}, [%4];"
                 : "=r"(r[0]), "=r"(r[1]), "=r"(r[2]), "=r"(r[3]) : "r"(addr));
}
__device__ __forceinline__ void ldm_x2t(uint* r, uint addr) {
    asm volatile("ldmatrix.sync.aligned.m8n8.x2.trans.shared.b16 {%0,%1}, [%2];"
                 : "=r"(r[0]), "=r"(r[1]) : "r"(addr));
}
__device__ __forceinline__ void mma_f16(float* c, const uint* a, const uint* b) {
    asm volatile(
        "mma.sync.aligned.m16n8k16.row.col.f32.f16.f16.f32 "
        "{%0,%1,%2,%3}, {%4,%5,%6,%7}, {%8,%9}, {%0,%1,%2,%3};"
        : "+f"(c[0]), "+f"(c[1]), "+f"(c[2]), "+f"(c[3])
        : "r"(a[0]), "r"(a[1]), "r"(a[2]), "r"(a[3]), "r"(b[0]), "r"(b[1]));
}

// ---------------------------------------------------------------------------
// Scratch (device globals)
// ---------------------------------------------------------------------------
__device__ float  g_s[B_ * CIN_];
__device__ float  g_ssq[B_ * CIN_];
__device__ float  g_wsqT[CIN_ * COUT_];
__device__ float  g_d[B_ * COUT_];
__device__ ushort g_xh[B_ * CIN_ * HW_];       // modulated x, fp16 (single-rounded)
__device__ ushort g_whi[9 * COUT_ * CIN_];     // weight hi fp16 per tap
__device__ ushort g_wlo[9 * COUT_ * CIN_];     // weight lo fp16 per tap

// ---------------------------------------------------------------------------
// Prep kernels
// ---------------------------------------------------------------------------
__global__ void style_kernel(const float* __restrict__ w,
                             const float* __restrict__ aw,
                             const float* __restrict__ ab) {
    int b = blockIdx.x;
    int c = threadIdx.x;
    __shared__ float wsh[WDIM_];
    wsh[c] = w[b * WDIM_ + c];
    __syncthreads();
    const float* awr = aw + (size_t)c * WDIM_;
    float acc = 0.f;
#pragma unroll 8
    for (int d = 0; d < WDIM_; ++d) acc += awr[d] * wsh[d];
    float s = acc + ab[c] + 1.0f;
    g_s[b * CIN_ + c] = s;
    g_ssq[b * CIN_ + c] = s * s;
}

__global__ void wsq_kernel(const float* __restrict__ weight) {
    int idx = blockIdx.x * blockDim.x + threadIdx.x;
    if (idx >= COUT_ * CIN_) return;
    const float* wp = weight + (size_t)idx * 9;
    float s = 0.f;
#pragma unroll
    for (int t = 0; t < 9; ++t) s += wp[t] * wp[t];
    g_wsqT[(idx & 511) * COUT_ + (idx >> 9)] = s;
}

__global__ void demod_kernel() {
    int b = blockIdx.x;
    int co = threadIdx.x;
    __shared__ float sq[CIN_];
    sq[co] = g_ssq[b * CIN_ + co];
    __syncthreads();
    float acc = 1e-8f;
#pragma unroll 8
    for (int ci = 0; ci < CIN_; ++ci)
        acc += sq[ci] * g_wsqT[ci * COUT_ + co];
    g_d[b * COUT_ + co] = rsqrtf(acc);
}

__global__ void split_x_kernel(const float* __restrict__ x) {
    int idx = blockIdx.x * 256 + threadIdx.x;
    int b = idx >> 21;
    int ci = (idx >> 12) & 511;
    g_xh[idx] = f16_of(x[idx] * g_s[b * CIN_ + ci]);
}

__global__ void split_w_kernel(const float* __restrict__ weight) {
    int idx = blockIdx.x * 256 + threadIdx.x;      // tap*512*512 + co*512 + ci
    int tap = idx >> 18;
    int co = (idx >> 9) & 511;
    int ci = idx & 511;
    float v = weight[((size_t)co * CIN_ + ci) * 9 + tap];
    ushort h = f16_of(v);
    float fh = __half2float(__ushort_as_half(h));
    ushort l = f16_of(v - fh);
    g_whi[idx] = h;
    g_wlo[idx] = l;
}

// ---------------------------------------------------------------------------
// Main conv: mma.sync fp16 implicit GEMM, 2-pass split (wh*x + wl*x),
// double-buffered pipeline, one __syncthreads per stage.
// CTA: 128 cout x 128 pixels (2 rows). 8 warps: wm=wid&3 (m32), wn=wid>>2 (n64).
// 288 stages: 32 cin-chunks x 9 taps, k16 each. 32 mma + 12 ldmatrix /warp/stage.
// ---------------------------------------------------------------------------
__global__ __launch_bounds__(256)
void modconv_mma_kernel(const float* __restrict__ noise,
                        const float* __restrict__ bias,
                        float* __restrict__ out) {
    __shared__ __align__(16) ushort Ahi[2][128][24], Alo[2][128][24];  // 24 KB
    __shared__ __align__(16) ushort Bf[2][16][136];                    // 8.5 KB

    const int t = threadIdx.x;
    const int lane = t & 31;
    const int wid = t >> 5;
    const int wm = wid & 3;
    const int wn = wid >> 2;
    const int b = blockIdx.z;
    const int co0 = blockIdx.x * 128;
    const int h0 = blockIdx.y * 2;

    float acc[2][8][4];
#pragma unroll
    for (int mt = 0; mt < 2; ++mt)
#pragma unroll
        for (int nt = 0; nt < 8; ++nt)
#pragma unroll
            for (int i = 0; i < 4; ++i) acc[mt][nt][i] = 0.f;

    const uint a_lane = (uint)((lane & 15) * 48 + (lane >> 4) * 16);
    const uint b_lane = (uint)((lane & 15) * 272);

    // build-thread maps
    const int am = t >> 1;            // A row (cout-sub)
    const int ak0 = (t & 1) * 8;      // A k offset (8 ushorts = 16B)
    const int bk = t >> 4;            // B k row
    const int bn0 = (t & 15) * 8;     // B pixel offset

    // staging regs
    uint4 ra_h, ra_l;
    ushort rb[8];

    auto load_stage = [&](int st) {
        const int chunk = st / 9;
        const int tap = st - chunk * 9;
        const int ci0 = chunk * 16;
        const size_t wbase = (((size_t)tap * 512 + co0 + am) << 9) + ci0 + ak0;
        ra_h = *(const uint4*)(g_whi + wbase);
        ra_l = *(const uint4*)(g_wlo + wbase);
        const int dy = tap / 3 - 1;
        const int dx = tap % 3 - 1;
        const int hh = h0 + (bn0 >> 6) + dy;
        const int wb = (bn0 & 63) + dx;
        if (hh >= 0 && hh < H_) {
            const ushort* xrow = g_xh + (((size_t)(b * CIN_ + ci0 + bk) * H_ + hh) << 6);
#pragma unroll
            for (int j = 0; j < 8; ++j) {
                int ww = wb + j;
                rb[j] = (ww >= 0 && ww < W_) ? xrow[ww] : (ushort)0;
            }
        } else {
#pragma unroll
            for (int j = 0; j < 8; ++j) rb[j] = (ushort)0;
        }
    };
    auto store_stage = [&](int buf) {
        *(uint4*)&Ahi[buf][am][ak0] = ra_h;
        *(uint4*)&Alo[buf][am][ak0] = ra_l;
        uint4 v;
        v.x = (uint)rb[0] | ((uint)rb[1] << 16);
        v.y = (uint)rb[2] | ((uint)rb[3] << 16);
        v.z = (uint)rb[4] | ((uint)rb[5] << 16);
        v.w = (uint)rb[6] | ((uint)rb[7] << 16);
        *(uint4*)&Bf[buf][bk][bn0] = v;
    };

    load_stage(0);
    store_stage(0);
    __syncthreads();

#pragma unroll 1
    for (int st = 0; st < 288; ++st) {
        const int buf = st & 1;
        if (st + 1 < 288) load_stage(st + 1);

        const uint AhiB = smem_u32(&Ahi[buf][0][0]);
        const uint AloB = smem_u32(&Alo[buf][0][0]);
        const uint BfB  = smem_u32(&Bf[buf][0][0]);
        uint ah[2][4], al[2][4];
#pragma unroll
        for (int mt = 0; mt < 2; ++mt) {
            uint mb = (uint)((wm * 32 + mt * 16) * 48);
            ldm_x4(ah[mt], AhiB + mb + a_lane);
            ldm_x4(al[mt], AloB + mb + a_lane);
        }
#pragma unroll
        for (int nt = 0; nt < 8; ++nt) {
            uint nb = (uint)((wn * 64 + nt * 8) * 2);
            uint bf[2];
            ldm_x2t(bf, BfB + b_lane + nb);
#pragma unroll
            for (int mt = 0; mt < 2; ++mt) {
                mma_f16(acc[mt][nt], ah[mt], bf);   // w_hi * x
                mma_f16(acc[mt][nt], al[mt], bf);   // w_lo * x
            }
        }

        if (st + 1 < 288) store_stage(buf ^ 1);
        __syncthreads();
    }

    // ---- epilogue: demod + noise + bias + leaky ----
    const int h = h0 + wn;
#pragma unroll
    for (int mt = 0; mt < 2; ++mt) {
        const int coa = co0 + wm * 32 + mt * 16 + (lane >> 2);
        const int cob = coa + 8;
        const float dda = g_d[b * COUT_ + coa], dba = bias[coa];
        const float ddb = g_d[b * COUT_ + cob], dbb = bias[cob];
        const size_t rowa = ((size_t)(b * COUT_ + coa) * H_ + h) * W_;
        const size_t rowb = ((size_t)(b * COUT_ + cob) * H_ + h) * W_;
#pragma unroll
        for (int nt = 0; nt < 8; ++nt) {
            const int wcol = nt * 8 + (lane & 3) * 2;
            float2 na = *(const float2*)(noise + rowa + wcol);
            float2 nb = *(const float2*)(noise + rowb + wcol);
            float r0 = dda * acc[mt][nt][0] + na.x + dba;
            float r1 = dda * acc[mt][nt][1] + na.y + dba;
            float r2 = ddb * acc[mt][nt][2] + nb.x + dbb;
            float r3 = ddb * acc[mt][nt][3] + nb.y + dbb;
            r0 = r0 >= 0.f ? r0 : 0.2f * r0;
            r1 = r1 >= 0.f ? r1 : 0.2f * r1;
            r2 = r2 >= 0.f ? r2 : 0.2f * r2;
            r3 = r3 >= 0.f ? r3 : 0.2f * r3;
            *(float2*)(out + rowa + wcol) = make_float2(r0, r1);
            *(float2*)(out + rowb + wcol) = make_float2(r2, r3);
        }
    }
}

// ---------------------------------------------------------------------------
// Launch. Inputs: x, w, noise, weight, affine_w, affine_b, bias
// ---------------------------------------------------------------------------
extern "C" void kernel_launch(void* const* d_in, const int* in_sizes, int n_in,
                              void* d_out, int out_size) {
    const float* x        = (const float*)d_in[0];
    const float* w        = (const float*)d_in[1];
    const float* noise    = (const float*)d_in[2];
    const float* weight   = (const float*)d_in[3];
    const float* affine_w = (const float*)d_in[4];
    const float* affine_b = (const float*)d_in[5];
    const float* bias     = (const float*)d_in[6];
    float* out = (float*)d_out;

    style_kernel<<<B_, CIN_>>>(w, affine_w, affine_b);
    wsq_kernel<<<(COUT_ * CIN_ + 255) / 256, 256>>>(weight);
    demod_kernel<<<B_, COUT_>>>();
    split_x_kernel<<<(B_ * CIN_ * HW_) / 256, 256>>>(x);
    split_w_kernel<<<(9 * COUT_ * CIN_) / 256, 256>>>(weight);

    dim3 grid(COUT_ / 128, H_ / 2, B_);   // (4, 32, 8) = 1024 CTAs
    modconv_mma_kernel<<<grid, 256>>>(noise, bias, out);
}